// round 16
// baseline (speedup 1.0000x reference)
#include <cuda_runtime.h>
#include <cuda_fp16.h>
#include <math.h>
#include <stdint.h>

typedef unsigned long long ull;

#define NN 4096
#define NE 8192
#define NG 256
#define OUTC 256
#define KP1 2176
#define KP2 8704
#define SPLITS 34

// ---------------- static device scratch ----------------
__device__ __half g_Ph[(size_t)NN * KP1];
__device__ __half g_Pl[(size_t)NN * KP1];
__device__ __half g_Wt1[(size_t)256 * KP1];
__device__ float g_h[NN * OUTC];
__device__ float g_Pm[(size_t)NG * KP2];             // per-graph mean of P2 (fp32)
__device__ float g_part[(size_t)SPLITS * NG * OUTC]; // split-K partials
__device__ int   g_off[NN + 1];
__device__ int   g_rank[NE];
__device__ int   g_csr[NE];
__device__ int   g_starts[NG + 1];
__device__ int   g_flag;                              // rank-done counter (self-resetting)

// ---------------- helpers ----------------
__device__ __forceinline__ uint32_t smem_u32(const void* p) {
    uint32_t a;
    asm("{ .reg .u64 t; cvta.to.shared.u64 t, %1; cvt.u32.u64 %0, t; }" : "=r"(a) : "l"(p));
    return a;
}
__device__ __forceinline__ void cp16(uint32_t dst, const void* src) {
    asm volatile("cp.async.cg.shared.global [%0], [%1], 16;" :: "r"(dst), "l"(src) : "memory");
}
__device__ __forceinline__ void cp_commit() {
    asm volatile("cp.async.commit_group;" ::: "memory");
}
template<int N>
__device__ __forceinline__ void cp_wait() {
    asm volatile("cp.async.wait_group %0;" :: "n"(N) : "memory");
}
__device__ __forceinline__ void ldsm4(uint32_t* r, uint32_t addr) {
    asm volatile("ldmatrix.sync.aligned.m8n8.x4.shared.b16 {%0,%1,%2,%3}, [%4];"
                 : "=r"(r[0]), "=r"(r[1]), "=r"(r[2]), "=r"(r[3]) : "r"(addr));
}
__device__ __forceinline__ void mma16816h(float* c, const uint32_t* a, const uint32_t* b) {
    asm volatile("mma.sync.aligned.m16n8k16.row.col.f32.f16.f16.f32 "
        "{%0,%1,%2,%3}, {%4,%5,%6,%7}, {%8,%9}, {%0,%1,%2,%3};"
        : "+f"(c[0]), "+f"(c[1]), "+f"(c[2]), "+f"(c[3])
        : "r"(a[0]), "r"(a[1]), "r"(a[2]), "r"(a[3]), "r"(b[0]), "r"(b[1]));
}
__device__ __forceinline__ uint32_t pack2h(__half a, __half b) {
    __half2 h = __halves2half2(a, b);
    return *(uint32_t*)&h;
}
__device__ __forceinline__ ull ffma2(ull a, ull b, ull c) {
    ull d; asm("fma.rn.f32x2 %0, %1, %2, %3;" : "=l"(d) : "l"(a), "l"(b), "l"(c)); return d;
}
__device__ __forceinline__ ull dup2(float v) {
    ull d; unsigned u = __float_as_uint(v);
    asm("mov.b64 %0, {%1, %1};" : "=l"(d) : "r"(u)); return d;
}
__device__ __forceinline__ void unpk(ull v, float &lo, float &hi) {
    asm("mov.b64 {%0, %1}, %2;" : "=f"(lo), "=f"(hi) : "l"(v));
}

// ---------------- kernel 1: fused CSR build ----------------
// blocks 0..7: rank (1024 edges each). block 8: starts + deg + scan, spin for ranks, place.
__global__ __launch_bounds__(1024) void csr_kernel(const int* __restrict__ dstA,
                                                   const int* __restrict__ batch) {
    const int t = threadIdx.x;
    if (blockIdx.x < 8) {
        __shared__ short sd[NE];
        for (int i = t; i < NE; i += 1024) sd[i] = (short)dstA[i];
        __syncthreads();
        const int e = blockIdx.x * 1024 + t;
        const int de = (int)sd[e];
        const uint32_t de2 = (uint32_t)(uint16_t)de | ((uint32_t)(uint16_t)de << 16);
        int r = 0, j = 0;
        const int e8 = e & ~7;
        for (; j < e8; j += 8) {
            uint4 v = *(const uint4*)&sd[j];
            r += __popc(__vcmpeq2(v.x, de2)) + __popc(__vcmpeq2(v.y, de2))
               + __popc(__vcmpeq2(v.z, de2)) + __popc(__vcmpeq2(v.w, de2));
        }
        r >>= 4;
        for (; j < e; j++) r += (sd[j] == (short)de) ? 1 : 0;
        g_rank[e] = r;
        __threadfence();
        __syncthreads();
        if (t == 0) atomicAdd(&g_flag, 1);
    } else {
        __shared__ int s[1024];
        __shared__ int arr[NN];
#pragma unroll
        for (int i = 0; i < 4; i++) arr[t * 4 + i] = 0;
        if (t <= NG) {
            int lo = 0, hi = NN;
            while (lo < hi) { int mid = (lo + hi) >> 1; if (batch[mid] < t) lo = mid + 1; else hi = mid; }
            g_starts[t] = lo;
        }
        __syncthreads();
        for (int e = t; e < NE; e += 1024) atomicAdd(&arr[dstA[e]], 1);
        __syncthreads();
        int l0 = arr[4 * t + 0], l1 = arr[4 * t + 1];
        int l2 = arr[4 * t + 2], l3 = arr[4 * t + 3];
        int tot = l0 + l1 + l2 + l3;
        s[t] = tot;
        __syncthreads();
        for (int off = 1; off < 1024; off <<= 1) {
            int v = (t >= off) ? s[t - off] : 0;
            __syncthreads();
            s[t] += v;
            __syncthreads();
        }
        int excl = s[t] - tot;
        arr[4 * t + 0] = excl;
        arr[4 * t + 1] = excl + l0;
        arr[4 * t + 2] = excl + l0 + l1;
        arr[4 * t + 3] = excl + l0 + l1 + l2;
        g_off[4 * t + 0] = excl;
        g_off[4 * t + 1] = excl + l0;
        g_off[4 * t + 2] = excl + l0 + l1;
        g_off[4 * t + 3] = excl + l0 + l1 + l2;
        if (t == 1023) g_off[NN] = excl + tot;
        // wait for all rank blocks, then reset flag for next graph replay
        if (t == 0) {
            while (atomicAdd(&g_flag, 0) < 8) { }
            atomicExch(&g_flag, 0);
        }
        __syncthreads();
        for (int e = t; e < NE; e += 1024)
            g_csr[arr[dstA[e]] + __ldcg(&g_rank[e])] = e;
    }
}

// ---------------- kernel 2: fused conv1 P scatter + weight prep ----------------
#define SMBUF_BYTES 12672
__global__ __launch_bounds__(256)
void scatter_prep_kernel(const float* __restrict__ xin, const float* __restrict__ eattr,
                         const int* __restrict__ srcA,
                         const float* __restrict__ Wm, const float* __restrict__ Wb,
                         const float* __restrict__ Wr)
{
    __shared__ __align__(16) char smbuf[SMBUF_BYTES];
    const int t = threadIdx.x;

    if (blockIdx.x >= NN) {
        float (*tile)[33] = (float(*)[33])smbuf;
        const int bid = blockIdx.x - NN;
        const int k0 = (bid % 68) * 32;
        const int o0 = (bid / 68) * 32;
        const int IC32 = 2048, IC33 = 2112;
        const int tx = t & 31, ty = t >> 5;
#pragma unroll
        for (int rr = 0; rr < 4; rr++) {
            int k = k0 + ty + rr * 8;
            const float* p = (k < IC32) ? Wm + (size_t)k * 256 + o0 + tx
                           : (k < IC33) ? Wb + (size_t)(k - IC32) * 256 + o0 + tx
                                        : Wr + (size_t)(k - IC33) * 256 + o0 + tx;
            tile[ty + rr * 8][tx] = *p;
        }
        __syncthreads();
#pragma unroll
        for (int rr = 0; rr < 4; rr++) {
            int o = o0 + ty + rr * 8;
            g_Wt1[(size_t)o * KP1 + k0 + tx] = __float2half_rn(tile[tx][ty + rr * 8]);
        }
        return;
    }

    constexpr int IC = 64;
    constexpr int KB = 33 * IC;
    constexpr int NT = (KB + 255) / 256;
    constexpr int CH = 8;
    float (*xs)[IC] = (float(*)[IC])(smbuf);
    float (*eas)[33] = (float(*)[33])(smbuf + 2048);
    int* sed = (int*)(smbuf + 4160);
    int* ssr = (int*)(smbuf + 4192);
    float* st = (float*)(smbuf + 4224);
    const int v = blockIdx.x;
    const int s = g_off[v], e = g_off[v + 1];

    float acc[NT];
#pragma unroll
    for (int i = 0; i < NT; i++) acc[i] = 0.f;

    for (int base = s; base < e; base += CH) {
        const int m = min(CH, e - base);
        __syncthreads();
        if (t < m) { int ed = g_csr[base + t]; sed[t] = ed; ssr[t] = srcA[ed]; }
        __syncthreads();
        for (int idx = t; idx < m * 33; idx += 256) {
            int j = idx / 33, d = idx - j * 33;
            eas[j][d] = (d < 32) ? eattr[sed[j] * 32 + d] : 1.0f;
        }
        for (int idx = t; idx < m * 16; idx += 256) {
            int j = idx >> 4, i = idx & 15;
            ((float4*)xs[j])[i] = ((const float4*)(xin + (size_t)ssr[j] * IC))[i];
        }
        __syncthreads();
#pragma unroll
        for (int ti = 0; ti < NT; ti++) {
            int k = t + ti * 256;
            if (k < KB) {
                int d = k >> 6, i = k & 63;
                float a = acc[ti];
                for (int j = 0; j < m; j++) a = fmaf(eas[j][d], xs[j][i], a);
                acc[ti] = a;
            }
        }
    }
#pragma unroll
    for (int ti = 0; ti < NT; ti++) {
        int k = t + ti * 256;
        if (k < KB) st[k] = acc[ti];
    }
    __syncthreads();
    __half* rh = g_Ph + (size_t)v * KP1;
    __half* rl = g_Pl + (size_t)v * KP1;
    for (int idx = t; idx < KB / 8; idx += 256) {
        const float* f = &st[idx * 8];
        __half hh[8]; uint4 hv, lv;
#pragma unroll
        for (int i = 0; i < 8; i++) hh[i] = __float2half_rn(f[i]);
        hv.x = pack2h(hh[0], hh[1]); hv.y = pack2h(hh[2], hh[3]);
        hv.z = pack2h(hh[4], hh[5]); hv.w = pack2h(hh[6], hh[7]);
        __half ll[8];
#pragma unroll
        for (int i = 0; i < 8; i++) ll[i] = __float2half_rn(f[i] - __half2float(hh[i]));
        lv.x = pack2h(ll[0], ll[1]); lv.y = pack2h(ll[2], ll[3]);
        lv.z = pack2h(ll[4], ll[5]); lv.w = pack2h(ll[6], ll[7]);
        *(uint4*)(rh + idx * 8) = hv;
        *(uint4*)(rl + idx * 8) = lv;
    }
    const float* xrow = xin + (size_t)v * IC;
    for (int idx = t; idx < IC / 8; idx += 256) {
        const float* f = xrow + idx * 8;
        __half hh[8]; uint4 hv, lv;
#pragma unroll
        for (int i = 0; i < 8; i++) hh[i] = __float2half_rn(f[i]);
        hv.x = pack2h(hh[0], hh[1]); hv.y = pack2h(hh[2], hh[3]);
        hv.z = pack2h(hh[4], hh[5]); hv.w = pack2h(hh[6], hh[7]);
        __half ll[8];
#pragma unroll
        for (int i = 0; i < 8; i++) ll[i] = __float2half_rn(f[i] - __half2float(hh[i]));
        lv.x = pack2h(ll[0], ll[1]); lv.y = pack2h(ll[2], ll[3]);
        lv.z = pack2h(ll[4], ll[5]); lv.w = pack2h(ll[6], ll[7]);
        *(uint4*)(rh + KB + idx * 8) = hv;
        *(uint4*)(rl + KB + idx * 8) = lv;
    }
}

// ---------------- kernel 3: conv1 GEMM (2-term fp16, 6-stage, 1 sync per 2 K-tiles) ----------
#define STG1 20480
#define GEMM1_SMEM (6 * STG1)
__global__ __launch_bounds__(256, 1)
void gemm1_mma(const __half* __restrict__ Ah, const __half* __restrict__ Al,
               const __half* __restrict__ B, const float* __restrict__ bias,
               float* __restrict__ out)
{
    constexpr int KP = KP1;
    constexpr int NK = KP / 32;   // 68 (even)
    constexpr int STG = STG1;
    extern __shared__ char smem[];
    const uint32_t sb = smem_u32(smem);
    const int t = threadIdx.x, lane = t & 31, wid = t >> 5;
    const int row0 = blockIdx.x * 128, col0 = blockIdx.y * 64;
    const int wm = (wid & 3) * 32, wn = (wid >> 2) * 32;

    float acc[2][4][4];
#pragma unroll
    for (int mf = 0; mf < 2; mf++)
#pragma unroll
        for (int nf = 0; nf < 4; nf++)
#pragma unroll
            for (int i = 0; i < 4; i++) acc[mf][nf][i] = 0.f;

    uint32_t a_addr[2][2], b_addr[2][2];
#pragma unroll
    for (int mf = 0; mf < 2; mf++)
#pragma unroll
        for (int g = 0; g < 2; g++) {
            int r = wm + mf * 16 + (lane & 7) + ((lane >> 3) & 1) * 8;
            int c = 2 * g + (lane >> 4);
            a_addr[mf][g] = (uint32_t)(r * 64 + ((c ^ ((r >> 1) & 3)) * 16));
        }
#pragma unroll
    for (int np = 0; np < 2; np++)
#pragma unroll
        for (int g = 0; g < 2; g++) {
            int r = wn + np * 16 + (lane & 7) + ((lane >> 4) & 1) * 8;
            int c = 2 * g + ((lane >> 3) & 1);
            b_addr[np][g] = (uint32_t)(16384 + r * 64 + ((c ^ ((r >> 1) & 3)) * 16));
        }

    const int ar0 = t >> 2;
    const int ac  = t & 3;
    const int br  = t >> 2;
    const uint32_t adst0 = (uint32_t)(ar0 * 64 + ((ac ^ ((ar0 >> 1) & 3)) * 16));
    const int ar1 = ar0 + 64;
    const uint32_t adst1 = (uint32_t)(ar1 * 64 + ((ac ^ ((ar1 >> 1) & 3)) * 16));
    const uint32_t bdst  = (uint32_t)(16384 + br * 64 + ((ac ^ ((br >> 1) & 3)) * 16));
    const __half* gah0 = Ah + (size_t)(row0 + ar0) * KP + ac * 8;
    const __half* gah1 = Ah + (size_t)(row0 + ar1) * KP + ac * 8;
    const __half* gal0 = Al + (size_t)(row0 + ar0) * KP + ac * 8;
    const __half* gal1 = Al + (size_t)(row0 + ar1) * KP + ac * 8;
    const __half* gb   = B  + (size_t)(col0 + br) * KP + ac * 8;

#define LOAD_STAGE(KT, S) do {                                   \
    uint32_t _sb = sb + (uint32_t)(S) * STG;                     \
    int _ko = (KT) * 32;                                         \
    cp16(_sb + adst0,        gah0 + _ko);                        \
    cp16(_sb + adst1,        gah1 + _ko);                        \
    cp16(_sb + adst0 + 8192, gal0 + _ko);                        \
    cp16(_sb + adst1 + 8192, gal1 + _ko);                        \
    cp16(_sb + bdst,         gb + _ko);                          \
    cp_commit();                                                 \
} while (0)

#define COMPUTE_KT(S) do {                                                     \
    const uint32_t sbase = sb + (uint32_t)(S) * STG;                           \
    _Pragma("unroll")                                                          \
    for (int g = 0; g < 2; g++) {                                              \
        uint32_t ah[2][4], al[2][4], bh[2][4];                                 \
        _Pragma("unroll")                                                      \
        for (int mf = 0; mf < 2; mf++) {                                       \
            ldsm4(ah[mf], sbase + a_addr[mf][g]);                              \
            ldsm4(al[mf], sbase + a_addr[mf][g] + 8192);                       \
        }                                                                      \
        _Pragma("unroll")                                                      \
        for (int np = 0; np < 2; np++) ldsm4(bh[np], sbase + b_addr[np][g]);   \
        _Pragma("unroll")                                                      \
        for (int mf = 0; mf < 2; mf++)                                         \
            _Pragma("unroll")                                                  \
            for (int nf = 0; nf < 4; nf++) {                                   \
                const uint32_t* pb = &bh[nf >> 1][(nf & 1) * 2];               \
                mma16816h(acc[mf][nf], ah[mf], pb);                            \
                mma16816h(acc[mf][nf], al[mf], pb);                            \
            }                                                                  \
    }                                                                          \
} while (0)

    LOAD_STAGE(0, 0);
    LOAD_STAGE(1, 1);
    LOAD_STAGE(2, 2);
    LOAD_STAGE(3, 3);

    for (int p = 0; p < NK; p += 2) {
        cp_wait<2>();
        __syncthreads();
        const int s0 = p % 6, s1 = (p + 1) % 6;
        COMPUTE_KT(s0);
        COMPUTE_KT(s1);
        if (p + 4 < NK) LOAD_STAGE(p + 4, (p + 4) % 6); else cp_commit();
        if (p + 5 < NK) LOAD_STAGE(p + 5, (p + 5) % 6); else cp_commit();
    }
#undef LOAD_STAGE
#undef COMPUTE_KT

#pragma unroll
    for (int mf = 0; mf < 2; mf++) {
        const int r0 = row0 + wm + mf * 16 + (lane >> 2);
#pragma unroll
        for (int nf = 0; nf < 4; nf++) {
            const int c = col0 + wn + nf * 8 + (lane & 3) * 2;
            float b0 = bias[c], b1 = bias[c + 1];
            float2 v0 = make_float2(fmaxf(acc[mf][nf][0] + b0, 0.f), fmaxf(acc[mf][nf][1] + b1, 0.f));
            float2 v1 = make_float2(fmaxf(acc[mf][nf][2] + b0, 0.f), fmaxf(acc[mf][nf][3] + b1, 0.f));
            *(float2*)(out + (size_t)r0 * 256 + c)       = v0;
            *(float2*)(out + (size_t)(r0 + 8) * 256 + c) = v1;
        }
    }
}

// ---------------- kernel 4 (PROFILED SLOT): conv2 graph-scatter ----------------
__global__ __launch_bounds__(256)
void gscatter_kernel(const float* __restrict__ eattr, const int* __restrict__ srcA)
{
    constexpr int CH = 8;
    __shared__ float hs[CH][256];
    __shared__ float eas[CH][33];
    __shared__ int sed[CH], ssr[CH];
    const int g = blockIdx.x, t = threadIdx.x;
    const int vs = g_starts[g], ve = g_starts[g + 1];
    const int es = g_off[vs], ee = g_off[ve];
    const float inv = 1.0f / (float)max(ve - vs, 1);

    float acc[33];
#pragma unroll
    for (int i = 0; i < 33; i++) acc[i] = 0.f;

    for (int base = es; base < ee; base += CH) {
        const int m = min(CH, ee - base);
        __syncthreads();
        if (t < m) { int ed = g_csr[base + t]; sed[t] = ed; ssr[t] = srcA[ed]; }
        __syncthreads();
        for (int idx = t; idx < m * 33; idx += 256) {
            int j = idx / 33, d = idx - j * 33;
            eas[j][d] = (d < 32) ? eattr[sed[j] * 32 + d] : 1.0f;
        }
        for (int idx = t; idx < m * 64; idx += 256) {
            int j = idx >> 6, i = idx & 63;
            ((float4*)hs[j])[i] = ((const float4*)(g_h + (size_t)ssr[j] * 256))[i];
        }
        __syncthreads();
        for (int j = 0; j < m; j++) {
            const float xv = hs[j][t];
#pragma unroll
            for (int d = 0; d < 33; d++) acc[d] = fmaf(eas[j][d], xv, acc[d]);
        }
    }
    float* pm = g_Pm + (size_t)g * KP2;
#pragma unroll
    for (int d = 0; d < 33; d++) pm[d * 256 + t] = acc[d] * inv;
    float sum = 0.f;
    for (int v = vs; v < ve; v++) sum += g_h[(size_t)v * 256 + t];
    pm[8448 + t] = sum * inv;
}

// ---------------- kernel 5: conv2 GEMM (fp32 f32x2, split-K, reg-prefetched) ----------------
__global__ __launch_bounds__(256)
void pgemm_kernel(const float* __restrict__ Wm, const float* __restrict__ Wb,
                  const float* __restrict__ Wr)
{
    __shared__ ull As2[16][128];
    __shared__ float Bs[16][128];
    const int t = threadIdx.x;
    const int ty = t >> 4, tx = t & 15;
    const int m0 = blockIdx.x * 128, n0 = blockIdx.y * 128;
    const int kbase = blockIdx.z * 256;

    ull acc[8][4];
#pragma unroll
    for (int r = 0; r < 8; r++)
#pragma unroll
        for (int c = 0; c < 4; c++) acc[r][c] = 0ull;

    const int lr = t >> 1, lc = (t & 1) * 8;
    const int bkk = t >> 4, bn = (t & 15) * 8;

    float4 a0, a1, b0, b1;
    {
        const int kc = kbase;
        a0 = *(const float4*)(g_Pm + (size_t)(m0 + lr) * KP2 + kc + lc);
        a1 = *(const float4*)(g_Pm + (size_t)(m0 + lr) * KP2 + kc + lc + 4);
        const int k = kc + bkk;
        const float* bp = (k < 8192) ? Wm + (size_t)k * 256 + n0 + bn
                        : (k < 8448) ? Wb + (size_t)(k - 8192) * 256 + n0 + bn
                                     : Wr + (size_t)(k - 8448) * 256 + n0 + bn;
        b0 = *(const float4*)bp;
        b1 = *(const float4*)(bp + 4);
    }

    for (int kt = 0; kt < 16; kt++) {
        __syncthreads();
        As2[lc + 0][lr] = dup2(a0.x); As2[lc + 1][lr] = dup2(a0.y);
        As2[lc + 2][lr] = dup2(a0.z); As2[lc + 3][lr] = dup2(a0.w);
        As2[lc + 4][lr] = dup2(a1.x); As2[lc + 5][lr] = dup2(a1.y);
        As2[lc + 6][lr] = dup2(a1.z); As2[lc + 7][lr] = dup2(a1.w);
        *(float4*)&Bs[bkk][bn] = b0;
        *(float4*)&Bs[bkk][bn + 4] = b1;
        __syncthreads();
        if (kt + 1 < 16) {
            const int kc = kbase + (kt + 1) * 16;
            a0 = *(const float4*)(g_Pm + (size_t)(m0 + lr) * KP2 + kc + lc);
            a1 = *(const float4*)(g_Pm + (size_t)(m0 + lr) * KP2 + kc + lc + 4);
            const int k = kc + bkk;
            const float* bp = (k < 8192) ? Wm + (size_t)k * 256 + n0 + bn
                            : (k < 8448) ? Wb + (size_t)(k - 8192) * 256 + n0 + bn
                                         : Wr + (size_t)(k - 8448) * 256 + n0 + bn;
            b0 = *(const float4*)bp;
            b1 = *(const float4*)(bp + 4);
        }
#pragma unroll
        for (int kk = 0; kk < 16; kk++) {
            ull a2[8], b2[4];
            *(ulonglong2*)&a2[0] = *(const ulonglong2*)&As2[kk][ty * 8 + 0];
            *(ulonglong2*)&a2[2] = *(const ulonglong2*)&As2[kk][ty * 8 + 2];
            *(ulonglong2*)&a2[4] = *(const ulonglong2*)&As2[kk][ty * 8 + 4];
            *(ulonglong2*)&a2[6] = *(const ulonglong2*)&As2[kk][ty * 8 + 6];
            *(ulonglong2*)&b2[0] = *(const ulonglong2*)&Bs[kk][tx * 8 + 0];
            *(ulonglong2*)&b2[2] = *(const ulonglong2*)&Bs[kk][tx * 8 + 4];
#pragma unroll
            for (int r = 0; r < 8; r++)
#pragma unroll
                for (int c = 0; c < 4; c++)
                    acc[r][c] = ffma2(a2[r], b2[c], acc[r][c]);
        }
    }
    float* po = g_part + (size_t)blockIdx.z * NG * OUTC;
#pragma unroll
    for (int r = 0; r < 8; r++) {
        const int row = m0 + ty * 8 + r;
        float4 v0, v1;
        unpk(acc[r][0], v0.x, v0.y); unpk(acc[r][1], v0.z, v0.w);
        unpk(acc[r][2], v1.x, v1.y); unpk(acc[r][3], v1.z, v1.w);
        *(float4*)(po + (size_t)row * OUTC + n0 + tx * 8)     = v0;
        *(float4*)(po + (size_t)row * OUTC + n0 + tx * 8 + 4) = v1;
    }
}

// ---------------- kernel 6: reduce partials + readout MLP + sigmoid ----------------
__global__ __launch_bounds__(256)
void pool_mlp_kernel(const float* __restrict__ bias2,
                     const float* __restrict__ l1w, const float* __restrict__ l1b,
                     const float* __restrict__ l2w, const float* __restrict__ l2b,
                     float* __restrict__ out)
{
    __shared__ float pooled[256];
    __shared__ float z[128];
    const int g = blockIdx.x, t = threadIdx.x;
    float s = bias2[t];
#pragma unroll
    for (int sp = 0; sp < SPLITS; sp++)
        s += g_part[(size_t)sp * NG * OUTC + (size_t)g * OUTC + t];
    pooled[t] = s;
    __syncthreads();
    if (t < 128) {
        float a = l1b[t];
#pragma unroll 8
        for (int o = 0; o < 256; o++) a = fmaf(pooled[o], l1w[o * 128 + t], a);
        z[t] = fmaxf(a, 0.f);
    }
    __syncthreads();
    if (t == 0) {
        float a = l2b[0];
#pragma unroll 8
        for (int j = 0; j < 128; j++) a = fmaf(z[j], l2w[j], a);
        out[g] = 1.0f / (1.0f + expf(-a));
    }
}

// ---------------- launch ----------------
extern "C" void kernel_launch(void* const* d_in, const int* in_sizes, int n_in,
                              void* d_out, int out_size)
{
    const float* x       = (const float*)d_in[0];
    const int*   ei      = (const int*)d_in[1];
    const float* ea      = (const float*)d_in[2];
    const int*   batch   = (const int*)d_in[3];
    const float* nn1_w   = (const float*)d_in[4];
    const float* nn1_b   = (const float*)d_in[5];
    const float* root1_w = (const float*)d_in[6];
    const float* bias1   = (const float*)d_in[7];
    const float* nn2_w   = (const float*)d_in[8];
    const float* nn2_b   = (const float*)d_in[9];
    const float* root2_w = (const float*)d_in[10];
    const float* bias2   = (const float*)d_in[11];
    const float* l1w     = (const float*)d_in[12];
    const float* l1b     = (const float*)d_in[13];
    const float* l2w     = (const float*)d_in[14];
    const float* l2b     = (const float*)d_in[15];
    const int* srcA = ei;
    const int* dstA = ei + NE;
    float* out = (float*)d_out;

    void *pPh, *pPl, *pW1, *ph;
    cudaGetSymbolAddress(&pPh, g_Ph);
    cudaGetSymbolAddress(&pPl, g_Pl);
    cudaGetSymbolAddress(&pW1, g_Wt1);
    cudaGetSymbolAddress(&ph, g_h);

    cudaFuncSetAttribute(gemm1_mma, cudaFuncAttributeMaxDynamicSharedMemorySize, GEMM1_SMEM);

    csr_kernel<<<9, 1024>>>(dstA, batch);                             // #1
    scatter_prep_kernel<<<NN + 544, 256>>>(x, ea, srcA,
                                           nn1_w, nn1_b, root1_w);    // #2
    gemm1_mma<<<dim3(32, 4), 256, GEMM1_SMEM>>>(                      // #3
        (const __half*)pPh, (const __half*)pPl, (const __half*)pW1, bias1, (float*)ph);
    gscatter_kernel<<<NG, 256>>>(ea, srcA);                           // #4 <- profiled
    pgemm_kernel<<<dim3(2, 2, SPLITS), 256>>>(nn2_w, nn2_b, root2_w); // #5
    pool_mlp_kernel<<<NG, 256>>>(bias2, l1w, l1b, l2w, l2b, out);     // #6
}

// round 17
// speedup vs baseline: 2.6837x; 2.6837x over previous
#include <cuda_runtime.h>
#include <cuda_fp16.h>
#include <math.h>
#include <stdint.h>

typedef unsigned long long ull;

#define NN 4096
#define NE 8192
#define NG 256
#define OUTC 256
#define KP1 2176
#define KP2 8704
#define SPLITS 34

// ---------------- static device scratch ----------------
__device__ __half g_Ph[(size_t)NN * KP1];
__device__ __half g_Pl[(size_t)NN * KP1];
__device__ __half g_Wt1[(size_t)256 * KP1];
__device__ float g_h[NN * OUTC];
__device__ float g_Pm[(size_t)NG * KP2];             // per-graph mean of P2 (fp32)
__device__ float g_part[(size_t)SPLITS * NG * OUTC]; // split-K partials
__device__ int   g_off[NN + 1];
__device__ int   g_rank[NE];
__device__ int   g_csr[NE];
__device__ int   g_starts[NG + 1];

// ---------------- helpers ----------------
__device__ __forceinline__ uint32_t smem_u32(const void* p) {
    uint32_t a;
    asm("{ .reg .u64 t; cvta.to.shared.u64 t, %1; cvt.u32.u64 %0, t; }" : "=r"(a) : "l"(p));
    return a;
}
__device__ __forceinline__ void cp16(uint32_t dst, const void* src) {
    asm volatile("cp.async.cg.shared.global [%0], [%1], 16;" :: "r"(dst), "l"(src) : "memory");
}
__device__ __forceinline__ void cp_commit() {
    asm volatile("cp.async.commit_group;" ::: "memory");
}
template<int N>
__device__ __forceinline__ void cp_wait() {
    asm volatile("cp.async.wait_group %0;" :: "n"(N) : "memory");
}
__device__ __forceinline__ void ldsm4(uint32_t* r, uint32_t addr) {
    asm volatile("ldmatrix.sync.aligned.m8n8.x4.shared.b16 {%0,%1,%2,%3}, [%4];"
                 : "=r"(r[0]), "=r"(r[1]), "=r"(r[2]), "=r"(r[3]) : "r"(addr));
}
__device__ __forceinline__ void mma16816h(float* c, const uint32_t* a, const uint32_t* b) {
    asm volatile("mma.sync.aligned.m16n8k16.row.col.f32.f16.f16.f32 "
        "{%0,%1,%2,%3}, {%4,%5,%6,%7}, {%8,%9}, {%0,%1,%2,%3};"
        : "+f"(c[0]), "+f"(c[1]), "+f"(c[2]), "+f"(c[3])
        : "r"(a[0]), "r"(a[1]), "r"(a[2]), "r"(a[3]), "r"(b[0]), "r"(b[1]));
}
__device__ __forceinline__ uint32_t pack2h(__half a, __half b) {
    __half2 h = __halves2half2(a, b);
    return *(uint32_t*)&h;
}
__device__ __forceinline__ ull ffma2(ull a, ull b, ull c) {
    ull d; asm("fma.rn.f32x2 %0, %1, %2, %3;" : "=l"(d) : "l"(a), "l"(b), "l"(c)); return d;
}
__device__ __forceinline__ ull dup2(float v) {
    ull d; unsigned u = __float_as_uint(v);
    asm("mov.b64 %0, {%1, %1};" : "=l"(d) : "r"(u)); return d;
}
__device__ __forceinline__ void unpk(ull v, float &lo, float &hi) {
    asm("mov.b64 {%0, %1}, %2;" : "=f"(lo), "=f"(hi) : "l"(v));
}

// ---------------- kernel 1: rank (stable position within dst bucket) ----------------
__global__ __launch_bounds__(256) void rank_kernel(const int* __restrict__ dstA) {
    __shared__ short sd[NE];
    const int t = threadIdx.x;
    for (int i = t; i < NE; i += 256) sd[i] = (short)dstA[i];
    __syncthreads();
    const int e = blockIdx.x * 256 + t;
    const int de = (int)sd[e];
    const uint32_t de2 = (uint32_t)(uint16_t)de | ((uint32_t)(uint16_t)de << 16);
    int r = 0, j = 0;
    const int e8 = e & ~7;
    for (; j < e8; j += 8) {
        uint4 v = *(const uint4*)&sd[j];
        r += __popc(__vcmpeq2(v.x, de2)) + __popc(__vcmpeq2(v.y, de2))
           + __popc(__vcmpeq2(v.z, de2)) + __popc(__vcmpeq2(v.w, de2));
    }
    r >>= 4;
    for (; j < e; j++) r += (sd[j] == (short)de) ? 1 : 0;
    g_rank[e] = r;
}

// ---------------- kernel 2: fused deg-count + scan + place + graph-starts ----------------
__global__ __launch_bounds__(1024) void scan_place_kernel(const int* __restrict__ dstA,
                                                          const int* __restrict__ batch) {
    __shared__ int s[1024];
    __shared__ int arr[NN];
    const int t = threadIdx.x;
#pragma unroll
    for (int i = 0; i < 4; i++) arr[t * 4 + i] = 0;
    if (t <= NG) {
        int lo = 0, hi = NN;
        while (lo < hi) { int mid = (lo + hi) >> 1; if (batch[mid] < t) lo = mid + 1; else hi = mid; }
        g_starts[t] = lo;
    }
    __syncthreads();
    for (int e = t; e < NE; e += 1024) atomicAdd(&arr[dstA[e]], 1);
    __syncthreads();
    int l0 = arr[4 * t + 0], l1 = arr[4 * t + 1];
    int l2 = arr[4 * t + 2], l3 = arr[4 * t + 3];
    int tot = l0 + l1 + l2 + l3;
    s[t] = tot;
    __syncthreads();
    for (int off = 1; off < 1024; off <<= 1) {
        int v = (t >= off) ? s[t - off] : 0;
        __syncthreads();
        s[t] += v;
        __syncthreads();
    }
    int excl = s[t] - tot;
    arr[4 * t + 0] = excl;
    arr[4 * t + 1] = excl + l0;
    arr[4 * t + 2] = excl + l0 + l1;
    arr[4 * t + 3] = excl + l0 + l1 + l2;
    g_off[4 * t + 0] = excl;
    g_off[4 * t + 1] = excl + l0;
    g_off[4 * t + 2] = excl + l0 + l1;
    g_off[4 * t + 3] = excl + l0 + l1 + l2;
    if (t == 1023) g_off[NN] = excl + tot;
    __syncthreads();
    for (int e = t; e < NE; e += 1024)
        g_csr[arr[dstA[e]] + g_rank[e]] = e;
}

// ---------------- kernel 3: fused conv1 P scatter + weight prep ----------------
#define SMBUF_BYTES 12672
__global__ __launch_bounds__(256)
void scatter_prep_kernel(const float* __restrict__ xin, const float* __restrict__ eattr,
                         const int* __restrict__ srcA,
                         const float* __restrict__ Wm, const float* __restrict__ Wb,
                         const float* __restrict__ Wr)
{
    __shared__ __align__(16) char smbuf[SMBUF_BYTES];
    const int t = threadIdx.x;

    if (blockIdx.x >= NN) {
        float (*tile)[33] = (float(*)[33])smbuf;
        const int bid = blockIdx.x - NN;
        const int k0 = (bid % 68) * 32;
        const int o0 = (bid / 68) * 32;
        const int IC32 = 2048, IC33 = 2112;
        const int tx = t & 31, ty = t >> 5;
#pragma unroll
        for (int rr = 0; rr < 4; rr++) {
            int k = k0 + ty + rr * 8;
            const float* p = (k < IC32) ? Wm + (size_t)k * 256 + o0 + tx
                           : (k < IC33) ? Wb + (size_t)(k - IC32) * 256 + o0 + tx
                                        : Wr + (size_t)(k - IC33) * 256 + o0 + tx;
            tile[ty + rr * 8][tx] = *p;
        }
        __syncthreads();
#pragma unroll
        for (int rr = 0; rr < 4; rr++) {
            int o = o0 + ty + rr * 8;
            g_Wt1[(size_t)o * KP1 + k0 + tx] = __float2half_rn(tile[tx][ty + rr * 8]);
        }
        return;
    }

    constexpr int IC = 64;
    constexpr int KB = 33 * IC;
    constexpr int NT = (KB + 255) / 256;
    constexpr int CH = 8;
    float (*xs)[IC] = (float(*)[IC])(smbuf);
    float (*eas)[33] = (float(*)[33])(smbuf + 2048);
    int* sed = (int*)(smbuf + 4160);
    int* ssr = (int*)(smbuf + 4192);
    float* st = (float*)(smbuf + 4224);
    const int v = blockIdx.x;
    const int s = g_off[v], e = g_off[v + 1];

    float acc[NT];
#pragma unroll
    for (int i = 0; i < NT; i++) acc[i] = 0.f;

    for (int base = s; base < e; base += CH) {
        const int m = min(CH, e - base);
        __syncthreads();
        if (t < m) { int ed = g_csr[base + t]; sed[t] = ed; ssr[t] = srcA[ed]; }
        __syncthreads();
        for (int idx = t; idx < m * 33; idx += 256) {
            int j = idx / 33, d = idx - j * 33;
            eas[j][d] = (d < 32) ? eattr[sed[j] * 32 + d] : 1.0f;
        }
        for (int idx = t; idx < m * 16; idx += 256) {
            int j = idx >> 4, i = idx & 15;
            ((float4*)xs[j])[i] = ((const float4*)(xin + (size_t)ssr[j] * IC))[i];
        }
        __syncthreads();
#pragma unroll
        for (int ti = 0; ti < NT; ti++) {
            int k = t + ti * 256;
            if (k < KB) {
                int d = k >> 6, i = k & 63;
                float a = acc[ti];
                for (int j = 0; j < m; j++) a = fmaf(eas[j][d], xs[j][i], a);
                acc[ti] = a;
            }
        }
    }
#pragma unroll
    for (int ti = 0; ti < NT; ti++) {
        int k = t + ti * 256;
        if (k < KB) st[k] = acc[ti];
    }
    __syncthreads();
    __half* rh = g_Ph + (size_t)v * KP1;
    __half* rl = g_Pl + (size_t)v * KP1;
    for (int idx = t; idx < KB / 8; idx += 256) {
        const float* f = &st[idx * 8];
        __half hh[8]; uint4 hv, lv;
#pragma unroll
        for (int i = 0; i < 8; i++) hh[i] = __float2half_rn(f[i]);
        hv.x = pack2h(hh[0], hh[1]); hv.y = pack2h(hh[2], hh[3]);
        hv.z = pack2h(hh[4], hh[5]); hv.w = pack2h(hh[6], hh[7]);
        __half ll[8];
#pragma unroll
        for (int i = 0; i < 8; i++) ll[i] = __float2half_rn(f[i] - __half2float(hh[i]));
        lv.x = pack2h(ll[0], ll[1]); lv.y = pack2h(ll[2], ll[3]);
        lv.z = pack2h(ll[4], ll[5]); lv.w = pack2h(ll[6], ll[7]);
        *(uint4*)(rh + idx * 8) = hv;
        *(uint4*)(rl + idx * 8) = lv;
    }
    const float* xrow = xin + (size_t)v * IC;
    for (int idx = t; idx < IC / 8; idx += 256) {
        const float* f = xrow + idx * 8;
        __half hh[8]; uint4 hv, lv;
#pragma unroll
        for (int i = 0; i < 8; i++) hh[i] = __float2half_rn(f[i]);
        hv.x = pack2h(hh[0], hh[1]); hv.y = pack2h(hh[2], hh[3]);
        hv.z = pack2h(hh[4], hh[5]); hv.w = pack2h(hh[6], hh[7]);
        __half ll[8];
#pragma unroll
        for (int i = 0; i < 8; i++) ll[i] = __float2half_rn(f[i] - __half2float(hh[i]));
        lv.x = pack2h(ll[0], ll[1]); lv.y = pack2h(ll[2], ll[3]);
        lv.z = pack2h(ll[4], ll[5]); lv.w = pack2h(ll[6], ll[7]);
        *(uint4*)(rh + KB + idx * 8) = hv;
        *(uint4*)(rl + KB + idx * 8) = lv;
    }
}

// ---------------- kernel 4 (PROFILED SLOT): conv1 GEMM (R13-proven 4-stage, 2-term fp16) ----
#define STG1 20480
#define GEMM1_SMEM (4 * STG1)
__global__ __launch_bounds__(256, 1)
void gemm1_mma(const __half* __restrict__ Ah, const __half* __restrict__ Al,
               const __half* __restrict__ B, const float* __restrict__ bias,
               float* __restrict__ out)
{
    constexpr int KP = KP1;
    constexpr int NK = KP / 32;   // 68
    constexpr int STG = STG1;
    extern __shared__ char smem[];
    const uint32_t sb = smem_u32(smem);
    const int t = threadIdx.x, lane = t & 31, wid = t >> 5;
    const int row0 = blockIdx.x * 128, col0 = blockIdx.y * 64;
    const int wm = (wid & 3) * 32, wn = (wid >> 2) * 32;

    float acc[2][4][4];
#pragma unroll
    for (int mf = 0; mf < 2; mf++)
#pragma unroll
        for (int nf = 0; nf < 4; nf++)
#pragma unroll
            for (int i = 0; i < 4; i++) acc[mf][nf][i] = 0.f;

    uint32_t a_addr[2][2], b_addr[2][2];
#pragma unroll
    for (int mf = 0; mf < 2; mf++)
#pragma unroll
        for (int g = 0; g < 2; g++) {
            int r = wm + mf * 16 + (lane & 7) + ((lane >> 3) & 1) * 8;
            int c = 2 * g + (lane >> 4);
            a_addr[mf][g] = (uint32_t)(r * 64 + ((c ^ ((r >> 1) & 3)) * 16));
        }
#pragma unroll
    for (int np = 0; np < 2; np++)
#pragma unroll
        for (int g = 0; g < 2; g++) {
            int r = wn + np * 16 + (lane & 7) + ((lane >> 4) & 1) * 8;
            int c = 2 * g + ((lane >> 3) & 1);
            b_addr[np][g] = (uint32_t)(16384 + r * 64 + ((c ^ ((r >> 1) & 3)) * 16));
        }

    const int ar0 = t >> 2;
    const int ac  = t & 3;
    const int br  = t >> 2;
    const uint32_t adst0 = (uint32_t)(ar0 * 64 + ((ac ^ ((ar0 >> 1) & 3)) * 16));
    const int ar1 = ar0 + 64;
    const uint32_t adst1 = (uint32_t)(ar1 * 64 + ((ac ^ ((ar1 >> 1) & 3)) * 16));
    const uint32_t bdst  = (uint32_t)(16384 + br * 64 + ((ac ^ ((br >> 1) & 3)) * 16));
    const __half* gah0 = Ah + (size_t)(row0 + ar0) * KP + ac * 8;
    const __half* gah1 = Ah + (size_t)(row0 + ar1) * KP + ac * 8;
    const __half* gal0 = Al + (size_t)(row0 + ar0) * KP + ac * 8;
    const __half* gal1 = Al + (size_t)(row0 + ar1) * KP + ac * 8;
    const __half* gb   = B  + (size_t)(col0 + br) * KP + ac * 8;

#define LOAD_STAGE(KT, S) do {                                   \
    uint32_t _sb = sb + (S) * STG;                               \
    int _ko = (KT) * 32;                                         \
    cp16(_sb + adst0,        gah0 + _ko);                        \
    cp16(_sb + adst1,        gah1 + _ko);                        \
    cp16(_sb + adst0 + 8192, gal0 + _ko);                        \
    cp16(_sb + adst1 + 8192, gal1 + _ko);                        \
    cp16(_sb + bdst,         gb + _ko);                          \
    cp_commit();                                                 \
} while (0)

    LOAD_STAGE(0, 0);
    LOAD_STAGE(1, 1);
    LOAD_STAGE(2, 2);

    for (int kt = 0; kt < NK; kt++) {
        cp_wait<2>();
        __syncthreads();
        const uint32_t sbase = sb + (kt & 3) * STG;
#pragma unroll
        for (int g = 0; g < 2; g++) {
            uint32_t ah[2][4], al[2][4], bh[2][4];
#pragma unroll
            for (int mf = 0; mf < 2; mf++) {
                ldsm4(ah[mf], sbase + a_addr[mf][g]);
                ldsm4(al[mf], sbase + a_addr[mf][g] + 8192);
            }
#pragma unroll
            for (int np = 0; np < 2; np++) ldsm4(bh[np], sbase + b_addr[np][g]);
#pragma unroll
            for (int mf = 0; mf < 2; mf++)
#pragma unroll
                for (int nf = 0; nf < 4; nf++) {
                    const uint32_t* pb = &bh[nf >> 1][(nf & 1) * 2];
                    mma16816h(acc[mf][nf], ah[mf], pb);
                    mma16816h(acc[mf][nf], al[mf], pb);
                }
        }
        if (kt + 3 < NK) LOAD_STAGE(kt + 3, (kt + 3) & 3);
        else cp_commit();
    }
#undef LOAD_STAGE

#pragma unroll
    for (int mf = 0; mf < 2; mf++) {
        const int r0 = row0 + wm + mf * 16 + (lane >> 2);
#pragma unroll
        for (int nf = 0; nf < 4; nf++) {
            const int c = col0 + wn + nf * 8 + (lane & 3) * 2;
            float b0 = bias[c], b1 = bias[c + 1];
            float2 v0 = make_float2(fmaxf(acc[mf][nf][0] + b0, 0.f), fmaxf(acc[mf][nf][1] + b1, 0.f));
            float2 v1 = make_float2(fmaxf(acc[mf][nf][2] + b0, 0.f), fmaxf(acc[mf][nf][3] + b1, 0.f));
            *(float2*)(out + (size_t)r0 * 256 + c)       = v0;
            *(float2*)(out + (size_t)(r0 + 8) * 256 + c) = v1;
        }
    }
}

// ---------------- kernel 5: conv2 graph-scatter (double-buffered cp.async) ----------------
// Same math/order as before (bit-identical): chunked CH=8 edge processing, but the h-row and
// edge-attr gathers for chunk c+1 are in flight (cp.async) during chunk c's compute.
#define MAXE 512
__global__ __launch_bounds__(256)
void gscatter_kernel(const float* __restrict__ eattr, const int* __restrict__ srcA)
{
    __shared__ __align__(16) float hs[2][8][256];  // 16 KB
    __shared__ __align__(16) float ea[2][8][32];   // 2 KB
    __shared__ int ssr[MAXE];
    __shared__ int sed[MAXE];
    const int g = blockIdx.x, t = threadIdx.x;
    const int vs = g_starts[g], ve = g_starts[g + 1];
    const int es = g_off[vs], ee = g_off[ve];
    const float inv = 1.0f / (float)max(ve - vs, 1);
    const uint32_t hs_base = smem_u32(&hs[0][0][0]);
    const uint32_t ea_base = smem_u32(&ea[0][0][0]);

    float acc[33];
#pragma unroll
    for (int i = 0; i < 33; i++) acc[i] = 0.f;

    for (int super = es; super < ee; super += MAXE) {
        const int E = min(MAXE, ee - super);
        __syncthreads();
        for (int i = t; i < E; i += 256) {
            int ed = g_csr[super + i];
            sed[i] = ed; ssr[i] = srcA[ed];
        }
        __syncthreads();
        const int C = (E + 7) / 8;

#define ISSUE_CHUNK(CI) do {                                                        \
    const int _b = (CI) & 1, _eb = (CI) * 8;                                        \
    const int _m = min(8, E - _eb);                                                 \
    for (int idx = t; idx < _m * 64; idx += 256) {                                  \
        int _j = idx >> 6, _p = idx & 63;                                           \
        cp16(hs_base + (uint32_t)((_b * 8 + _j) * 1024 + _p * 16),                  \
             g_h + (size_t)ssr[_eb + _j] * 256 + _p * 4);                           \
    }                                                                               \
    for (int idx = t; idx < _m * 8; idx += 256) {                                   \
        int _j = idx >> 3, _p = idx & 7;                                            \
        cp16(ea_base + (uint32_t)((_b * 8 + _j) * 128 + _p * 16),                   \
             eattr + (size_t)sed[_eb + _j] * 32 + _p * 4);                          \
    }                                                                               \
    cp_commit();                                                                    \
} while (0)

        ISSUE_CHUNK(0);
        for (int c = 0; c < C; c++) {
            __syncthreads();                 // all warps done with the buffer chunk c+1 will overwrite
            if (c + 1 < C) { ISSUE_CHUNK(c + 1); cp_wait<1>(); }
            else           { cp_wait<0>(); }
            __syncthreads();                 // chunk c resident for everyone
            const int b = c & 1, ebase = c * 8;
            const int m = min(8, E - ebase);
            for (int j = 0; j < m; j++) {
                const float xv = hs[b][j][t];
#pragma unroll
                for (int d = 0; d < 32; d++) acc[d] = fmaf(ea[b][j][d], xv, acc[d]);
                acc[32] += xv;
            }
        }
#undef ISSUE_CHUNK
    }

    float* pm = g_Pm + (size_t)g * KP2;
#pragma unroll
    for (int d = 0; d < 33; d++) pm[d * 256 + t] = acc[d] * inv;
    float sum = 0.f;
    for (int v = vs; v < ve; v++) sum += g_h[(size_t)v * 256 + t];
    pm[8448 + t] = sum * inv;
}

// ---------------- kernel 6: conv2 GEMM (fp32 f32x2, split-K, reg-prefetched) ----------------
__global__ __launch_bounds__(256)
void pgemm_kernel(const float* __restrict__ Wm, const float* __restrict__ Wb,
                  const float* __restrict__ Wr)
{
    __shared__ ull As2[16][128];
    __shared__ float Bs[16][128];
    const int t = threadIdx.x;
    const int ty = t >> 4, tx = t & 15;
    const int m0 = blockIdx.x * 128, n0 = blockIdx.y * 128;
    const int kbase = blockIdx.z * 256;

    ull acc[8][4];
#pragma unroll
    for (int r = 0; r < 8; r++)
#pragma unroll
        for (int c = 0; c < 4; c++) acc[r][c] = 0ull;

    const int lr = t >> 1, lc = (t & 1) * 8;
    const int bkk = t >> 4, bn = (t & 15) * 8;

    float4 a0, a1, b0, b1;
    {
        const int kc = kbase;
        a0 = *(const float4*)(g_Pm + (size_t)(m0 + lr) * KP2 + kc + lc);
        a1 = *(const float4*)(g_Pm + (size_t)(m0 + lr) * KP2 + kc + lc + 4);
        const int k = kc + bkk;
        const float* bp = (k < 8192) ? Wm + (size_t)k * 256 + n0 + bn
                        : (k < 8448) ? Wb + (size_t)(k - 8192) * 256 + n0 + bn
                                     : Wr + (size_t)(k - 8448) * 256 + n0 + bn;
        b0 = *(const float4*)bp;
        b1 = *(const float4*)(bp + 4);
    }

    for (int kt = 0; kt < 16; kt++) {
        __syncthreads();
        As2[lc + 0][lr] = dup2(a0.x); As2[lc + 1][lr] = dup2(a0.y);
        As2[lc + 2][lr] = dup2(a0.z); As2[lc + 3][lr] = dup2(a0.w);
        As2[lc + 4][lr] = dup2(a1.x); As2[lc + 5][lr] = dup2(a1.y);
        As2[lc + 6][lr] = dup2(a1.z); As2[lc + 7][lr] = dup2(a1.w);
        *(float4*)&Bs[bkk][bn] = b0;
        *(float4*)&Bs[bkk][bn + 4] = b1;
        __syncthreads();
        if (kt + 1 < 16) {
            const int kc = kbase + (kt + 1) * 16;
            a0 = *(const float4*)(g_Pm + (size_t)(m0 + lr) * KP2 + kc + lc);
            a1 = *(const float4*)(g_Pm + (size_t)(m0 + lr) * KP2 + kc + lc + 4);
            const int k = kc + bkk;
            const float* bp = (k < 8192) ? Wm + (size_t)k * 256 + n0 + bn
                            : (k < 8448) ? Wb + (size_t)(k - 8192) * 256 + n0 + bn
                                         : Wr + (size_t)(k - 8448) * 256 + n0 + bn;
            b0 = *(const float4*)bp;
            b1 = *(const float4*)(bp + 4);
        }
#pragma unroll
        for (int kk = 0; kk < 16; kk++) {
            ull a2[8], b2[4];
            *(ulonglong2*)&a2[0] = *(const ulonglong2*)&As2[kk][ty * 8 + 0];
            *(ulonglong2*)&a2[2] = *(const ulonglong2*)&As2[kk][ty * 8 + 2];
            *(ulonglong2*)&a2[4] = *(const ulonglong2*)&As2[kk][ty * 8 + 4];
            *(ulonglong2*)&a2[6] = *(const ulonglong2*)&As2[kk][ty * 8 + 6];
            *(ulonglong2*)&b2[0] = *(const ulonglong2*)&Bs[kk][tx * 8 + 0];
            *(ulonglong2*)&b2[2] = *(const ulonglong2*)&Bs[kk][tx * 8 + 4];
#pragma unroll
            for (int r = 0; r < 8; r++)
#pragma unroll
                for (int c = 0; c < 4; c++)
                    acc[r][c] = ffma2(a2[r], b2[c], acc[r][c]);
        }
    }
    float* po = g_part + (size_t)blockIdx.z * NG * OUTC;
#pragma unroll
    for (int r = 0; r < 8; r++) {
        const int row = m0 + ty * 8 + r;
        float4 v0, v1;
        unpk(acc[r][0], v0.x, v0.y); unpk(acc[r][1], v0.z, v0.w);
        unpk(acc[r][2], v1.x, v1.y); unpk(acc[r][3], v1.z, v1.w);
        *(float4*)(po + (size_t)row * OUTC + n0 + tx * 8)     = v0;
        *(float4*)(po + (size_t)row * OUTC + n0 + tx * 8 + 4) = v1;
    }
}

// ---------------- kernel 7: reduce partials + readout MLP + sigmoid ----------------
__global__ __launch_bounds__(256)
void pool_mlp_kernel(const float* __restrict__ bias2,
                     const float* __restrict__ l1w, const float* __restrict__ l1b,
                     const float* __restrict__ l2w, const float* __restrict__ l2b,
                     float* __restrict__ out)
{
    __shared__ float pooled[256];
    __shared__ float z[128];
    const int g = blockIdx.x, t = threadIdx.x;
    float s = bias2[t];
#pragma unroll
    for (int sp = 0; sp < SPLITS; sp++)
        s += g_part[(size_t)sp * NG * OUTC + (size_t)g * OUTC + t];
    pooled[t] = s;
    __syncthreads();
    if (t < 128) {
        float a = l1b[t];
#pragma unroll 8
        for (int o = 0; o < 256; o++) a = fmaf(pooled[o], l1w[o * 128 + t], a);
        z[t] = fmaxf(a, 0.f);
    }
    __syncthreads();
    if (t == 0) {
        float a = l2b[0];
#pragma unroll 8
        for (int j = 0; j < 128; j++) a = fmaf(z[j], l2w[j], a);
        out[g] = 1.0f / (1.0f + expf(-a));
    }
}

// ---------------- launch ----------------
extern "C" void kernel_launch(void* const* d_in, const int* in_sizes, int n_in,
                              void* d_out, int out_size)
{
    const float* x       = (const float*)d_in[0];
    const int*   ei      = (const int*)d_in[1];
    const float* ea      = (const float*)d_in[2];
    const int*   batch   = (const int*)d_in[3];
    const float* nn1_w   = (const float*)d_in[4];
    const float* nn1_b   = (const float*)d_in[5];
    const float* root1_w = (const float*)d_in[6];
    const float* bias1   = (const float*)d_in[7];
    const float* nn2_w   = (const float*)d_in[8];
    const float* nn2_b   = (const float*)d_in[9];
    const float* root2_w = (const float*)d_in[10];
    const float* bias2   = (const float*)d_in[11];
    const float* l1w     = (const float*)d_in[12];
    const float* l1b     = (const float*)d_in[13];
    const float* l2w     = (const float*)d_in[14];
    const float* l2b     = (const float*)d_in[15];
    const int* srcA = ei;
    const int* dstA = ei + NE;
    float* out = (float*)d_out;

    void *pPh, *pPl, *pW1, *ph;
    cudaGetSymbolAddress(&pPh, g_Ph);
    cudaGetSymbolAddress(&pPl, g_Pl);
    cudaGetSymbolAddress(&pW1, g_Wt1);
    cudaGetSymbolAddress(&ph, g_h);

    cudaFuncSetAttribute(gemm1_mma, cudaFuncAttributeMaxDynamicSharedMemorySize, GEMM1_SMEM);

    rank_kernel<<<32, 256>>>(dstA);                                   // #1
    scan_place_kernel<<<1, 1024>>>(dstA, batch);                      // #2
    scatter_prep_kernel<<<NN + 544, 256>>>(x, ea, srcA,
                                           nn1_w, nn1_b, root1_w);    // #3
    gemm1_mma<<<dim3(32, 4), 256, GEMM1_SMEM>>>(                      // #4 <- profiled
        (const __half*)pPh, (const __half*)pPl, (const __half*)pW1, bias1, (float*)ph);
    gscatter_kernel<<<NG, 256>>>(ea, srcA);                           // #5
    pgemm_kernel<<<dim3(2, 2, SPLITS), 256>>>(nn2_w, nn2_b, root2_w); // #6
    pool_mlp_kernel<<<NG, 256>>>(bias2, l1w, l1b, l2w, l2b, out);     // #7
}